// round 16
// baseline (speedup 1.0000x reference)
#include <cuda_runtime.h>
#include <cuda_bf16.h>
#include <math.h>
#include <stdint.h>

#define N_TOK 16384
#define DM 1024
#define EM 8
#define HM 256

// ---- arch-specific feature detection (tcgen05 availability) -------------------
#if defined(__CUDA_ARCH__) && (__CUDA_ARCH__ == 1000 || __CUDA_ARCH__ == 1030) && \
    (defined(__CUDA_ARCH_FEAT_SM100_ALL) || defined(__CUDA_ARCH_FEAT_SM103_ALL) || \
     defined(__CUDA_ARCH_SPECIFIC__) || defined(__CUDA_ARCH_FAMILY_SPECIFIC__))
#define TC_PATH 1
#else
#define TC_PATH 0
#endif

// ---------------- scratch -------------------------------------------------------
__device__ float g_xa[(size_t)N_TOK * DM];               // fallback tf32 A (token order)
__device__ float g_h[(size_t)N_TOK * HM];                // fallback tf32 h
__device__ float g_w1t[(size_t)EM * DM * HM];            // fallback tf32 W1
__device__ float g_w2t[(size_t)EM * HM * DM];            // fallback tf32 W2
__device__ __nv_bfloat16 g_a_hi[(size_t)N_TOK * DM];     // tc: A hi/lo (token order)
__device__ __nv_bfloat16 g_a_lo[(size_t)N_TOK * DM];
// tc: weight blobs = exact swizzled SMEM stage images
__device__ __align__(16) uint4 g_w1b[(size_t)EM * 32 * 2048];  // 8MB
__device__ __align__(16) uint4 g_w2b[(size_t)EM * 64 * 1024];  // 8MB
__device__ int g_top1[N_TOK];
__device__ int g_rank[N_TOK];
__device__ int g_perm[N_TOK];
__device__ int g_counts[EM];

// ---------------- helpers -------------------------------------------------------
__device__ __forceinline__ uint32_t s2u(const void* p) {
    return (uint32_t)__cvta_generic_to_shared(p);
}
__device__ __forceinline__ uint32_t f2tf(float f) {
    uint32_t u;
    asm("cvt.rna.tf32.f32 %0, %1;" : "=r"(u) : "f"(f));
    return u;
}
__device__ __forceinline__ void cpa16(uint32_t dst, const void* src) {
    asm volatile("cp.async.cg.shared.global [%0], [%1], 16;" ::"r"(dst), "l"(src));
}
__device__ __forceinline__ void cpa_commit() { asm volatile("cp.async.commit_group;"); }
__device__ __forceinline__ void cpa_wait4() { asm volatile("cp.async.wait_group 4;"); }
__device__ __forceinline__ void cpa_wait3() { asm volatile("cp.async.wait_group 3;"); }
__device__ __forceinline__ void cpa_wait2() { asm volatile("cp.async.wait_group 2;"); }
__device__ __forceinline__ void cpa_wait1() { asm volatile("cp.async.wait_group 1;"); }
__device__ __forceinline__ void cpa_wait0() { asm volatile("cp.async.wait_group 0;"); }

__device__ __forceinline__ uint32_t bfpack(__nv_bfloat16 a, __nv_bfloat16 b) {
    uint16_t ua = *(uint16_t*)&a, ub = *(uint16_t*)&b;
    return (uint32_t)ua | ((uint32_t)ub << 16);
}
__device__ __forceinline__ void bfsplit(float v, __nv_bfloat16& h, __nv_bfloat16& l) {
    h = __float2bfloat16(v);
    l = __float2bfloat16(v - __bfloat162float(h));
}

// tile -> (expert, row0, rows) from g_counts
__device__ __forceinline__ bool map_tile(int bx, int& e_out, int& row0_out,
                                         int& rows_out) {
    int acc = 0, off = 0, e = -1, row0 = 0, rows = 0;
#pragma unroll
    for (int i = 0; i < EM; i++) {
        int cnt = g_counts[i];
        int te = (cnt + 127) >> 7;
        if (e < 0 && bx < acc + te) {
            int tm = bx - acc;
            e = i;
            row0 = off + tm * 128;
            rows = cnt - tm * 128;
            if (rows > 128) rows = 128;
        }
        acc += te;
        off += cnt;
    }
    e_out = e;
    row0_out = row0;
    rows_out = rows;
    return e >= 0;
}

// ---------------- 1: fused router + LN + split (one warp per token) ---------------
__global__ __launch_bounds__(256) void k_router(const float* __restrict__ x,
                                                const float* __restrict__ Wg,
                                                const float* __restrict__ ls,
                                                const float* __restrict__ lb) {
    const int warp = threadIdx.x >> 5, lane = threadIdx.x & 31;
    const int n = blockIdx.x * 8 + warp;
    const float4* xr = (const float4*)(x + (size_t)n * DM);
    const float4* wg = (const float4*)Wg;

    float s = 0.f, ss = 0.f;
    float lg[EM];
#pragma unroll
    for (int e = 0; e < EM; e++) lg[e] = 0.f;
    float4 xv[8];
#pragma unroll
    for (int j = 0; j < 8; j++) {
        float4 v = xr[lane + 32 * j];
        xv[j] = v;
        s += v.x + v.y + v.z + v.w;
        ss += v.x * v.x + v.y * v.y + v.z * v.z + v.w * v.w;
#pragma unroll
        for (int e = 0; e < EM; e++) {
            float4 w = wg[e * 256 + lane + 32 * j];
            lg[e] += v.x * w.x + v.y * w.y + v.z * w.z + v.w * w.w;
        }
    }
#pragma unroll
    for (int o = 16; o > 0; o >>= 1) {
        s  += __shfl_xor_sync(0xffffffffu, s, o);
        ss += __shfl_xor_sync(0xffffffffu, ss, o);
#pragma unroll
        for (int e = 0; e < EM; e++)
            lg[e] += __shfl_xor_sync(0xffffffffu, lg[e], o);
    }
    float mu = s / (float)DM;
    float var = ss / (float)DM - mu * mu;
    float rs = rsqrtf(var + 1e-5f);
    int best = 0;
    float bv = lg[0];
#pragma unroll
    for (int e = 1; e < EM; e++)
        if (lg[e] > bv) { bv = lg[e]; best = e; }
    if (lane == 0) {
        g_top1[n] = best;
        g_rank[n] = atomicAdd(&g_counts[best], 1);
    }
    const float4* lsr = (const float4*)(ls + (size_t)best * DM);
    const float4* lbr = (const float4*)(lb + (size_t)best * DM);
#pragma unroll
    for (int j = 0; j < 8; j++) {
        float4 sv = lsr[lane + 32 * j];
        float4 bb = lbr[lane + 32 * j];
        float v0 = (xv[j].x - mu) * rs * sv.x + bb.x;
        float v1 = (xv[j].y - mu) * rs * sv.y + bb.y;
        float v2 = (xv[j].z - mu) * rs * sv.z + bb.z;
        float v3 = (xv[j].w - mu) * rs * sv.w + bb.w;
        size_t idx = (size_t)n * DM + 4 * (lane + 32 * j);
#if TC_PATH
        __nv_bfloat16 h0, h1, h2, h3, l0, l1, l2, l3;
        bfsplit(v0, h0, l0);
        bfsplit(v1, h1, l1);
        bfsplit(v2, h2, l2);
        bfsplit(v3, h3, l3);
        *(uint2*)(g_a_hi + idx) = make_uint2(bfpack(h0, h1), bfpack(h2, h3));
        *(uint2*)(g_a_lo + idx) = make_uint2(bfpack(l0, l1), bfpack(l2, l3));
#else
        float4 o;
        o.x = __uint_as_float(f2tf(v0));
        o.y = __uint_as_float(f2tf(v1));
        o.z = __uint_as_float(f2tf(v2));
        o.w = __uint_as_float(f2tf(v3));
        *(float4*)(g_xa + idx) = o;
#endif
    }
}

// ---------------- 2: perm --------------------------------------------------------
__global__ __launch_bounds__(256) void k_perm() {
    int n = blockIdx.x * 256 + threadIdx.x;
    int e = g_top1[n];
    int off = 0;
#pragma unroll
    for (int i = 0; i < EM; i++)
        if (i < e) off += g_counts[i];
    g_perm[off + g_rank[n]] = n;
}

// ---------------- 3: weight prep (-> swizzled stage blobs) -------------------------
#define SWZH(o) ((o) ^ (((o) >> 3) & 0x70u))
__global__ __launch_bounds__(256) void k_wprep(const float* __restrict__ W1,
                                               const float* __restrict__ W2) {
#if TC_PATH
    __shared__ float t[32][33];
    const int e = blockIdx.y;
    const int bx = blockIdx.x;
    const int tid = threadIdx.x;
    const int tx = tid & 31, ty = tid >> 5;

    const float* src;
    uint4* dstBlob;
    int colbase, rowloc_base;
    if (bx < 256) {
        int s = bx >> 3, rblk = bx & 7;
        src = W1 + (size_t)e * DM * HM + (size_t)(s * 32) * HM + rblk * 32;
        dstBlob = g_w1b + (size_t)(e * 32 + s) * 2048;
        colbase = HM;
        rowloc_base = rblk * 32;
    } else {
        int idx = bx - 256;
        int g = idx >> 2, rblk2 = idx & 3;
        int cch = g >> 3, s2 = g & 7;
        src = W2 + (size_t)e * HM * DM + (size_t)(s2 * 32) * DM + cch * 128 + rblk2 * 32;
        dstBlob = g_w2b + (size_t)(e * 64 + g) * 1024;
        colbase = DM;
        rowloc_base = rblk2 * 32;
    }
#pragma unroll
    for (int j = 0; j < 4; j++)
        t[ty + 8 * j][tx] = src[(size_t)(ty + 8 * j) * colbase + tx];
    __syncthreads();
    const int rloc = tid >> 3, c8 = tid & 7;
    const int kc = (c8 & 3) * 8;
    const bool hi = c8 < 4;
    uint32_t w[4];
#pragma unroll
    for (int q = 0; q < 4; q++) {
        __nv_bfloat16 ha, la, hb, lc;
        bfsplit(t[kc + 2 * q][rloc], ha, la);
        bfsplit(t[kc + 2 * q + 1][rloc], hb, lc);
        w[q] = hi ? bfpack(ha, hb) : bfpack(la, lc);
    }
    uint32_t off = SWZH((uint32_t)((rowloc_base + rloc) * 128 + c8 * 16));
    dstBlob[off >> 4] = make_uint4(w[0], w[1], w[2], w[3]);
#else
    const int HALF = EM * DM * HM / 4;
    int id = (blockIdx.y * 512 + blockIdx.x) * 256 + threadIdx.x;
    const float4* src = (id < HALF) ? (const float4*)W1 : (const float4*)W2;
    float4* dst = (id < HALF) ? (float4*)g_w1t : (float4*)g_w2t;
    int i = (id < HALF) ? id : id - HALF;
    float4 v = src[i];
    float4 o;
    o.x = __uint_as_float(f2tf(v.x));
    o.y = __uint_as_float(f2tf(v.y));
    o.z = __uint_as_float(f2tf(v.z));
    o.w = __uint_as_float(f2tf(v.w));
    dst[i] = o;
#endif
}

// =====================================================================================
// tcgen05 machinery
// =====================================================================================
#if TC_PATH
#define SWZ(o) ((o) ^ (((o) >> 3) & 0x70u))
__device__ __forceinline__ bool elect_one() {
    uint32_t pred;
    asm volatile(
        "{\n\t.reg .pred p;\n\telect.sync _|p, 0xFFFFFFFF;\n\tselp.b32 %0, 1, 0, p;\n\t}"
        : "=r"(pred));
    return pred != 0;
}
__device__ __forceinline__ void mbar_wait(uint32_t addr, uint32_t parity) {
    asm volatile(
        "{\n\t"
        ".reg .pred P;\n\t"
        "LAB_%=:\n\t"
        "mbarrier.try_wait.parity.acquire.cta.shared::cta.b64 P, [%0], %1;\n\t"
        "@!P bra LAB_%=;\n\t"
        "}"
        :: "r"(addr), "r"(parity) : "memory");
}
__device__ __forceinline__ void expect_tx(uint32_t mbar, uint32_t bytes) {
    asm volatile("mbarrier.arrive.expect_tx.shared.b64 _, [%0], %1;"
                 :: "r"(mbar), "r"(bytes) : "memory");
}
__device__ __forceinline__ void bulk_g2s(uint32_t dst, const void* src,
                                         uint32_t bytes, uint32_t mbar) {
    asm volatile(
        "cp.async.bulk.shared::cta.global.mbarrier::complete_tx::bytes [%0], [%1], %2, [%3];"
        :: "r"(dst), "l"(src), "r"(bytes), "r"(mbar) : "memory");
}
__device__ __forceinline__ void mma_ss_f16(uint32_t d, uint64_t ad, uint64_t bd,
                                           uint32_t idesc, uint32_t en) {
    asm volatile(
        "{\n\t"
        ".reg .pred p;\n\t"
        "setp.ne.u32 p, %4, 0;\n\t"
        "tcgen05.mma.cta_group::1.kind::f16 [%0], %1, %2, %3, {%5, %5, %5, %5}, p;\n\t"
        "}"
        :: "r"(d), "l"(ad), "l"(bd), "r"(idesc), "r"(en), "r"(0u)
        : "memory");
}
#define LDTM32(r, a)                                                         \
    asm volatile(                                                            \
        "tcgen05.ld.sync.aligned.32x32b.x32.b32 "                            \
        "{%0, %1, %2, %3, %4, %5, %6, %7, "                                  \
        " %8, %9, %10, %11, %12, %13, %14, %15, "                            \
        " %16, %17, %18, %19, %20, %21, %22, %23, "                          \
        " %24, %25, %26, %27, %28, %29, %30, %31}, [%32];"                   \
        : "=r"((r)[0]), "=r"((r)[1]), "=r"((r)[2]), "=r"((r)[3]),            \
          "=r"((r)[4]), "=r"((r)[5]), "=r"((r)[6]), "=r"((r)[7]),            \
          "=r"((r)[8]), "=r"((r)[9]), "=r"((r)[10]), "=r"((r)[11]),          \
          "=r"((r)[12]), "=r"((r)[13]), "=r"((r)[14]), "=r"((r)[15]),        \
          "=r"((r)[16]), "=r"((r)[17]), "=r"((r)[18]), "=r"((r)[19]),        \
          "=r"((r)[20]), "=r"((r)[21]), "=r"((r)[22]), "=r"((r)[23]),        \
          "=r"((r)[24]), "=r"((r)[25]), "=r"((r)[26]), "=r"((r)[27]),        \
          "=r"((r)[28]), "=r"((r)[29]), "=r"((r)[30]), "=r"((r)[31])         \
        : "r"(a))

#define DESCB ((2ULL << 61) | (1ULL << 46) | (64ULL << 32) | (1ULL << 16))
#define IDESC1 0x8400490u   // N=256, M=128
#define IDESC2 0x8200490u   // N=128, M=128
#define A_SLOT 16384        // one A stage (128 rows x 128B), ring of 6: 0..96K
#define B1_BASE 98304       // GEMM1 B ring: 4 x 32KB: 96K..224K
#define STG1B 32768
#define H_BLK 16384         // h blocks: sb+0..128K (after GEMM1 done)
#define B2_BASE 131072      // GEMM2 B ring: 4 x 16KB: 128K..192K
#endif

#define SMEM_ALLOC (229376 + 1024)   // 224KB rings + align pad

// fallback tiling
#define BK 32
#define AS_STR 36
#define BS_STR 136
#define A_STAGE (128 * AS_STR)
#define B_STAGE (BK * BS_STR)
#define NSTG 3

#if !TC_PATH
__device__ __forceinline__ void mma8(float* c, const uint32_t* a, const uint32_t* b) {
    asm volatile(
        "mma.sync.aligned.m16n8k8.row.col.f32.tf32.tf32.f32 "
        "{%0,%1,%2,%3},{%4,%5,%6,%7},{%8,%9},{%0,%1,%2,%3};"
        : "+f"(c[0]), "+f"(c[1]), "+f"(c[2]), "+f"(c[3])
        : "r"(a[0]), "r"(a[1]), "r"(a[2]), "r"(a[3]), "r"(b[0]), "r"(b[1]));
}
__device__ __forceinline__ void fb_load_stage(uint32_t smem_u32, int stg,
                                              const float* Ag, int ldA, int row0,
                                              int rows, const int* prow,
                                              const float* Bg, int ldB,
                                              int col0, int k0, int tid) {
    uint32_t as_b = smem_u32 + (uint32_t)stg * (A_STAGE * 4);
    uint32_t bs_b = smem_u32 + (uint32_t)(NSTG * A_STAGE + stg * B_STAGE) * 4;
#pragma unroll
    for (int i = 0; i < 4; i++) {
        int id = tid + 256 * i;
        int r = id >> 3, kc = (id & 7) * 4;
        int rr = (r < rows) ? r : rows - 1;
        int grow = prow ? prow[rr] : (row0 + rr);
        cpa16(as_b + (uint32_t)(r * AS_STR + kc) * 4,
              Ag + (size_t)grow * ldA + k0 + kc);
    }
#pragma unroll
    for (int i = 0; i < 4; i++) {
        int id = tid + 256 * i;
        int kr = id >> 5, nc = (id & 31) * 4;
        cpa16(bs_b + (uint32_t)(kr * BS_STR + nc) * 4,
              Bg + (size_t)(k0 + kr) * ldB + col0 + nc);
    }
}
__device__ __forceinline__ void fb_compute_stage(const uint32_t* smem, int stg,
                                                 int wm, int wn, int g, int t,
                                                 float c[2][8][4]) {
    const uint32_t* As = smem + stg * A_STAGE;
    const uint32_t* Bs = smem + NSTG * A_STAGE + stg * B_STAGE;
#pragma unroll
    for (int ks = 0; ks < BK; ks += 8) {
        uint32_t a[2][4], b[8][2];
#pragma unroll
        for (int mt = 0; mt < 2; mt++) {
            int m = wm * 32 + mt * 16 + g;
            a[mt][0] = As[m * AS_STR + ks + t];
            a[mt][1] = As[(m + 8) * AS_STR + ks + t];
            a[mt][2] = As[m * AS_STR + ks + t + 4];
            a[mt][3] = As[(m + 8) * AS_STR + ks + t + 4];
        }
#pragma unroll
        for (int nt = 0; nt < 8; nt++) {
            int n = wn * 64 + nt * 8 + g;
            b[nt][0] = Bs[(ks + t) * BS_STR + n];
            b[nt][1] = Bs[(ks + t + 4) * BS_STR + n];
        }
#pragma unroll
        for (int mt = 0; mt < 2; mt++)
#pragma unroll
            for (int nt = 0; nt < 8; nt++)
                mma8(c[mt][nt], a[mt], b[nt]);
    }
}
#endif

// ---------------- 4: fused FFN (GEMM1 -> GELU -> SMEM h -> GEMM2) ------------------
// grid 136, 256 threads
__global__ __launch_bounds__(256) void k_ffn(const float* __restrict__ b1,
                                             const float* __restrict__ b2,
                                             float* __restrict__ out) {
    extern __shared__ __align__(16) char dsm[];

    int e, row0, rows;
    bool valid = map_tile(blockIdx.x, e, row0, rows);
    const int tid = threadIdx.x, wid = tid >> 5, lane = tid & 31;

#if TC_PATH
    if (valid) {
    __shared__ uint32_t s_tslot;
    // [0,1]=commit gating, [2..5]=tx (B bulk), [6..9]=gemm2 empty, [10]=chunk
    __shared__ __align__(8) uint64_t s_mbar[11];
    uint32_t sb = s2u(dsm);
    sb = (sb + 1023u) & ~1023u;
    const uint32_t mb0 = s2u(&s_mbar[0]);
    const uint32_t mb1 = s2u(&s_mbar[1]);
    const uint32_t mbT = s2u(&s_mbar[2]);
    const uint32_t mbE = s2u(&s_mbar[6]);
    const uint32_t mbC = s2u(&s_mbar[10]);
    const uint32_t tslot = s2u(&s_tslot);

    if (wid == 0) {
        asm volatile("tcgen05.alloc.cta_group::1.sync.aligned.shared::cta.b32 [%0], %1;"
                     :: "r"(tslot), "r"(256) : "memory");
        asm volatile("tcgen05.relinquish_alloc_permit.cta_group::1.sync.aligned;");
    }
    if (tid == 0) {
        asm volatile("mbarrier.init.shared.b64 [%0], 1;" :: "r"(mb0) : "memory");
        asm volatile("mbarrier.init.shared.b64 [%0], 1;" :: "r"(mb1) : "memory");
#pragma unroll
        for (int i = 0; i < 4; i++) {
            asm volatile("mbarrier.init.shared.b64 [%0], 1;" :: "r"(mbT + 8 * i) : "memory");
            asm volatile("mbarrier.init.shared.b64 [%0], 1;" :: "r"(mbE + 8 * i) : "memory");
        }
        asm volatile("mbarrier.init.shared.b64 [%0], 1;" :: "r"(mbC) : "memory");
    }
    __syncthreads();
    uint32_t tb;
    asm volatile("ld.shared.b32 %0, [%1];" : "=r"(tb) : "r"(tslot));
    uint32_t ph[2] = {0u, 0u};
    uint32_t fph = 0u;   // tx barrier parity bits (elect only)
    uint32_t eph = 0u;   // gemm2 empty parity bits (elect only)
    uint32_t cph = 0u;

    const uint4* w1blob = g_w1b + (size_t)e * 32 * 2048;
    const uint4* w2blob = g_w2b + (size_t)e * 64 * 1024;

    // ---------------- GEMM1: A (deep cp.async ring) x W1 blob (bulk) ----------------
    const int c8 = tid & 7;
    const bool chi = (c8 < 4);
    {
        const __nv_bfloat16* Asrc[4];
        uint32_t Adst[4];
        const int cq = (c8 & 3) * 8;
#pragma unroll
        for (int i = 0; i < 4; i++) {
            int r = (tid >> 3) + 32 * i;
            int rr = (r < rows) ? r : rows - 1;
            int tok = g_perm[row0 + rr];
            Asrc[i] = (chi ? g_a_hi : g_a_lo) + (size_t)tok * DM + cq;
            Adst[i] = SWZ((uint32_t)(r * 128 + c8 * 16));
        }
        auto loadA = [&](int s) {
            uint32_t base = sb + (uint32_t)(s % 6) * A_SLOT;
            int k0 = s * 32;
#pragma unroll
            for (int i = 0; i < 4; i++)
                cpa16(base + Adst[i], Asrc[i] + k0);
            cpa_commit();
        };

        const int S = DM / 32;  // 32
        int ni1 = 0;
        loadA(0);
        loadA(1);
        loadA(2);
        loadA(3);
        for (int s = 0; s < S; s++) {
            if (s >= 2) {
                uint32_t m = (s & 1) ? mb1 : mb0;
                mbar_wait(m, ph[s & 1]);
                ph[s & 1] ^= 1;
            }
            // commit(s-2) freed A slot (s-2)%6 == (s+4)%6 and B slot (s+2)&3
            if (s + 4 < S) loadA(s + 4);
            if (s + 4 < S) cpa_wait4();
            else if (s + 3 < S) cpa_wait3();
            else if (s + 2 < S) cpa_wait2();
            else if (s + 1 < S) cpa_wait1();
            else cpa_wait0();
            __syncthreads();
            if (wid == 0) {
                asm volatile("fence.proxy.async.shared::cta;" ::: "memory");
                if (elect_one()) {
                    while (ni1 < S && ni1 <= s + 2) {
                        uint32_t mt = mbT + 8 * (ni1 & 3);
                        expect_tx(mt, 32768u);
                        bulk_g2s(sb + B1_BASE + (uint32_t)(ni1 & 3) * STG1B,
                                 w1blob + (size_t)ni1 * 2048, 32768u, mt);
                        ni1++;
                    }
                    mbar_wait(mbT + 8 * (s & 3), (fph >> (s & 3)) & 1u);
                    fph ^= 1u << (s & 3);
                    uint64_t ab = DESCB |
                        ((uint64_t)((sb + (uint32_t)(s % 6) * A_SLOT) >> 4) & 0x3FFF);
                    uint64_t bb = DESCB |
                        ((uint64_t)((sb + B1_BASE + (uint32_t)(s & 3) * STG1B) >> 4) & 0x3FFF);
#pragma unroll
                    for (int ks = 0; ks < 2; ks++) {
                        uint64_t ah = ab + 2 * ks, al = ab + 4 + 2 * ks;
                        uint64_t bh = bb + 2 * ks, bl = bb + 4 + 2 * ks;
                        mma_ss_f16(tb, ah, bh, IDESC1, (s == 0 && ks == 0) ? 0u : 1u);
                        mma_ss_f16(tb, ah, bl, IDESC1, 1u);
                        mma_ss_f16(tb, al, bh, IDESC1, 1u);
                    }
                    uint32_t m = (s & 1) ? mb1 : mb0;
                    asm volatile(
                        "tcgen05.commit.cta_group::1.mbarrier::arrive::one.shared::cluster.b64 [%0];"
                        :: "r"(m) : "memory");
                }
            }
        }
        {
            uint32_t mA = (32 & 1) ? mb1 : mb0;
            mbar_wait(mA, ph[0]);
            ph[0] ^= 1;
            uint32_t mB = mb1;
            mbar_wait(mB, ph[1]);
            ph[1] ^= 1;
        }
        asm volatile("tcgen05.fence::after_thread_sync;" ::: "memory");
    }

    // ---------------- GEMM1 epilogue: bias + GELU -> SMEM h -------------------------
    {
        int rl = (wid & 3) * 32 + lane;
        int ccb = (wid >> 2) * 4;
        const float* bbp = b1 + e * HM;
#pragma unroll 1
        for (int ci = 0; ci < 4; ci++) {
            int cc = ccb + ci;
            uint32_t r[32];
            LDTM32(r, tb + cc * 32);
            asm volatile("tcgen05.wait::ld.sync.aligned;" ::: "memory");
            uint32_t whi[16], wlo[16];
#pragma unroll
            for (int p = 0; p < 16; p++) {
                float v0 = __uint_as_float(r[2 * p]) + __ldg(&bbp[cc * 32 + 2 * p]);
                float v1 = __uint_as_float(r[2 * p + 1]) + __ldg(&bbp[cc * 32 + 2 * p + 1]);
                v0 = 0.5f * v0 * (1.f + erff(v0 * 0.70710678118654752f));
                v1 = 0.5f * v1 * (1.f + erff(v1 * 0.70710678118654752f));
                __nv_bfloat16 h0, h1, l0, l1;
                bfsplit(v0, h0, l0);
                bfsplit(v1, h1, l1);
                whi[p] = bfpack(h0, h1);
                wlo[p] = bfpack(l0, l1);
            }
            uint32_t blk = sb + (uint32_t)cc * H_BLK;
#pragma unroll
            for (int q = 0; q < 4; q++) {
                uint32_t ohi = blk + SWZ((uint32_t)(rl * 128 + 16 * q));
                uint32_t olo = blk + SWZ((uint32_t)(rl * 128 + 64 + 16 * q));
                asm volatile("st.shared.v4.b32 [%0], {%1,%2,%3,%4};"
                             :: "r"(ohi), "r"(whi[4 * q]), "r"(whi[4 * q + 1]),
                                "r"(whi[4 * q + 2]), "r"(whi[4 * q + 3]) : "memory");
                asm volatile("st.shared.v4.b32 [%0], {%1,%2,%3,%4};"
                             :: "r"(olo), "r"(wlo[4 * q]), "r"(wlo[4 * q + 1]),
                                "r"(wlo[4 * q + 2]), "r"(wlo[4 * q + 3]) : "memory");
            }
        }
    }
    asm volatile("fence.proxy.async.shared::cta;" ::: "memory");
    __syncthreads();

    // ---------------- GEMM2: h(SMEM) x W2 blobs (bulk) -> out ------------------------
    {
        int rl = (wid & 3) * 32 + lane;
        bool ok = rl < rows;
        int tok = ok ? g_perm[row0 + rl] : 0;
        float* orow = out + (size_t)tok * DM;
        int ni2 = 0;

        for (int cch = 0; cch < 8; cch++) {
            if (wid == 0 && elect_one()) {
#pragma unroll 1
                for (int s = 0; s < 8; s++) {
                    int g = cch * 8 + s;
                    while (ni2 < 64 && ni2 <= g + 3) {
                        if (ni2 >= 4) {
                            mbar_wait(mbE + 8 * (ni2 & 3), (eph >> (ni2 & 3)) & 1u);
                            eph ^= 1u << (ni2 & 3);
                        }
                        uint32_t mt = mbT + 8 * (ni2 & 3);
                        expect_tx(mt, 16384u);
                        bulk_g2s(sb + B2_BASE + (uint32_t)(ni2 & 3) * H_BLK,
                                 w2blob + (size_t)ni2 * 1024, 16384u, mt);
                        ni2++;
                    }
                    mbar_wait(mbT + 8 * (g & 3), (fph >> (g & 3)) & 1u);
                    fph ^= 1u << (g & 3);
                    uint64_t ab = DESCB | ((uint64_t)((sb + (uint32_t)s * H_BLK) >> 4) & 0x3FFF);
                    uint64_t bbd = DESCB |
                        ((uint64_t)((sb + B2_BASE + (uint32_t)(g & 3) * H_BLK) >> 4) & 0x3FFF);
#pragma unroll
                    for (int ks = 0; ks < 2; ks++) {
                        uint64_t ah = ab + 2 * ks, al = ab + 4 + 2 * ks;
                        uint64_t bh = bbd + 2 * ks, bl = bbd + 4 + 2 * ks;
                        uint32_t en = (s == 0 && ks == 0) ? 0u : 1u;
                        mma_ss_f16(tb, ah, bh, IDESC2, en);
                        mma_ss_f16(tb, ah, bl, IDESC2, 1u);
                        mma_ss_f16(tb, al, bh, IDESC2, 1u);
                    }
                    asm volatile(
                        "tcgen05.commit.cta_group::1.mbarrier::arrive::one.shared::cluster.b64 [%0];"
                        :: "r"(mbE + 8 * (g & 3)) : "memory");
                    if (s == 7)
                        asm volatile(
                            "tcgen05.commit.cta_group::1.mbarrier::arrive::one.shared::cluster.b64 [%0];"
                            :: "r"(mbC) : "memory");
                }
            }
            mbar_wait(mbC, cph);
            cph ^= 1u;
            asm volatile("tcgen05.fence::after_thread_sync;" ::: "memory");
            {
                int colh = (wid >> 2) * 64;
                const float* bbp = b2 + e * DM + cch * 128 + colh;
#pragma unroll 1
                for (int half = 0; half < 2; half++) {
                    uint32_t r[32];
                    LDTM32(r, tb + colh + half * 32);
                    asm volatile("tcgen05.wait::ld.sync.aligned;" ::: "memory");
                    if (ok) {
#pragma unroll
                        for (int q = 0; q < 8; q++) {
                            float4 v;
                            v.x = __uint_as_float(r[4 * q + 0]) + __ldg(&bbp[half * 32 + 4 * q + 0]);
                            v.y = __uint_as_float(r[4 * q + 1]) + __ldg(&bbp[half * 32 + 4 * q + 1]);
                            v.z = __uint_as_float(r[4 * q + 2]) + __ldg(&bbp[half * 32 + 4 * q + 2]);
                            v.w = __uint_as_float(r[4 * q + 3]) + __ldg(&bbp[half * 32 + 4 * q + 3]);
                            *(float4*)(orow + cch * 128 + colh + half * 32 + 4 * q) = v;
                        }
                    }
                }
            }
            __syncthreads();
        }
    }
    if (wid == 0)
        asm volatile("tcgen05.dealloc.cta_group::1.sync.aligned.b32 %0, %1;"
                     :: "r"(tb), "r"(256));
    }  // valid
#else
    if (valid) {
    uint32_t* smem = (uint32_t*)dsm;
    const uint32_t smem_u32 = s2u(dsm);
    const int* prow = g_perm + row0;
    const int w = wid, wm = w >> 1, wn = w & 1;
    const int g = lane >> 2, tt = lane & 3;

    for (int hseg = 0; hseg < 2; hseg++) {
        int col0 = hseg * 128;
        const float* Ag = g_xa;
        const float* Bg = g_w1t + (size_t)e * DM * HM;
        float cacc[2][8][4];
#pragma unroll
        for (int i = 0; i < 2; i++)
#pragma unroll
            for (int j = 0; j < 8; j++)
#pragma unroll
                for (int q = 0; q < 4; q++) cacc[i][j][q] = 0.f;
        const int S = DM / BK;
        __syncthreads();
        fb_load_stage(smem_u32, 0, Ag, DM, row0, rows, prow, Bg, HM, col0, 0, tid);
        cpa_commit();
        fb_load_stage(smem_u32, 1, Ag, DM, row0, rows, prow, Bg, HM, col0, BK, tid);
        cpa_commit();
        for (int s = 0; s < S; s++) {
            if (s + 1 < S) cpa_wait1(); else cpa_wait0();
            __syncthreads();
            if (s + 2 < S) {
                fb_load_stage(smem_u32, (s + 2) % NSTG, Ag, DM, row0, rows, prow,
                              Bg, HM, col0, (s + 2) * BK, tid);
                cpa_commit();
            }
            fb_compute_stage(smem, s % NSTG, wm, wn, g, tt, cacc);
        }
#pragma unroll
        for (int mt = 0; mt < 2; mt++) {
            int rl0 = wm * 32 + mt * 16 + g;
#pragma unroll
            for (int half = 0; half < 2; half++) {
                int rl = rl0 + 8 * half;
                if (rl < rows) {
                    size_t orw = (size_t)(row0 + rl) * HM;
#pragma unroll
                    for (int nt = 0; nt < 8; nt++) {
                        int col = col0 + wn * 64 + nt * 8 + 2 * tt;
                        float v0 = cacc[mt][nt][2 * half + 0] + __ldg(&b1[e * HM + col]);
                        float v1 = cacc[mt][nt][2 * half + 1] + __ldg(&b1[e * HM + col + 1]);
                        v0 = 0.5f * v0 * (1.f + erff(v0 * 0.70710678118654752f));
                        v1 = 0.5f * v1 * (1.f + erff(v1 * 0.70710678118654752f));
                        float2 o = make_float2(__uint_as_float(f2tf(v0)),
                                               __uint_as_float(f2tf(v1)));
                        *(float2*)&g_h[orw + col] = o;
                    }
                }
            }
        }
        __syncthreads();
    }

    for (int ct = 0; ct < 8; ct++) {
        int col0 = ct * 128;
        const float* Ag = g_h;
        const float* Bg = g_w2t + (size_t)e * HM * DM;
        float cacc[2][8][4];
#pragma unroll
        for (int i = 0; i < 2; i++)
#pragma unroll
            for (int j = 0; j < 8; j++)
#pragma unroll
                for (int q = 0; q < 4; q++) cacc[i][j][q] = 0.f;
        const int S = HM / BK;
        __syncthreads();
        fb_load_stage(smem_u32, 0, Ag, HM, row0, rows, nullptr, Bg, DM, col0, 0, tid);
        cpa_commit();
        fb_load_stage(smem_u32, 1, Ag, HM, row0, rows, nullptr, Bg, DM, col0, BK, tid);
        cpa_commit();
        for (int s = 0; s < S; s++) {
            if (s + 1 < S) cpa_wait1(); else cpa_wait0();
            __syncthreads();
            if (s + 2 < S) {
                fb_load_stage(smem_u32, (s + 2) % NSTG, Ag, HM, row0, rows, nullptr,
                              Bg, DM, col0, (s + 2) * BK, tid);
                cpa_commit();
            }
            fb_compute_stage(smem, s % NSTG, wm, wn, g, tt, cacc);
        }
#pragma unroll
        for (int mt = 0; mt < 2; mt++) {
            int rl0 = wm * 32 + mt * 16 + g;
#pragma unroll
            for (int half = 0; half < 2; half++) {
                int rl = rl0 + 8 * half;
                if (rl < rows) {
                    int tok = g_perm[row0 + rl];
                    float* orw = out + (size_t)tok * DM;
#pragma unroll
                    for (int nt = 0; nt < 8; nt++) {
                        int col = col0 + wn * 64 + nt * 8 + 2 * tt;
                        float v0 = cacc[mt][nt][2 * half + 0] + __ldg(&b2[e * DM + col]);
                        float v1 = cacc[mt][nt][2 * half + 1] + __ldg(&b2[e * DM + col + 1]);
                        *(float2*)&orw[col] = make_float2(v0, v1);
                    }
                }
            }
        }
        __syncthreads();
    }
    }  // valid
#endif
    // reset counters for next graph replay
    __syncthreads();
    if (blockIdx.x == 0 && tid < EM) g_counts[tid] = 0;
}

// ---------------- launch -----------------------------------------------------------------
extern "C" void kernel_launch(void* const* d_in, const int* in_sizes, int n_in,
                              void* d_out, int out_size) {
    (void)in_sizes; (void)n_in; (void)out_size;
    const float* x  = (const float*)d_in[0];
    const float* Wg = (const float*)d_in[1];
    const float* ls = (const float*)d_in[2];
    const float* lb = (const float*)d_in[3];
    const float* W1 = (const float*)d_in[4];
    const float* b1 = (const float*)d_in[5];
    const float* W2 = (const float*)d_in[6];
    const float* b2 = (const float*)d_in[7];
    float* out = (float*)d_out;

    cudaFuncSetAttribute(k_ffn, cudaFuncAttributeMaxDynamicSharedMemorySize, SMEM_ALLOC);

    static cudaStream_t s1 = nullptr;
    static cudaEvent_t ev_fork = nullptr, ev_join = nullptr;
    static bool stream_ok = false;
    static bool tried = false;
    if (!tried) {
        tried = true;
        if (cudaStreamCreateWithFlags(&s1, cudaStreamNonBlocking) == cudaSuccess &&
            cudaEventCreateWithFlags(&ev_fork, cudaEventDisableTiming) == cudaSuccess &&
            cudaEventCreateWithFlags(&ev_join, cudaEventDisableTiming) == cudaSuccess)
            stream_ok = true;
    }

    const int MAX_TILES = (N_TOK / 128) + EM;  // 136

    if (stream_ok) {
        cudaEventRecord(ev_fork, 0);
        cudaStreamWaitEvent(s1, ev_fork, 0);
        k_wprep<<<dim3(512, EM), 256, 0, s1>>>(W1, W2);
        cudaEventRecord(ev_join, s1);
    }
    k_router<<<N_TOK / 8, 256>>>(x, Wg, ls, lb);
    k_perm<<<N_TOK / 256, 256>>>();
    if (stream_ok) {
        cudaStreamWaitEvent(0, ev_join, 0);
    } else {
        k_wprep<<<dim3(512, EM), 256>>>(W1, W2);
    }
    k_ffn<<<MAX_TILES, 256, SMEM_ALLOC>>>(b1, b2, out);
}

// round 17
// speedup vs baseline: 1.0305x; 1.0305x over previous
#include <cuda_runtime.h>
#include <cuda_bf16.h>
#include <math.h>
#include <stdint.h>

#define N_TOK 16384
#define DM 1024
#define EM 8
#define HM 256

// ---- arch-specific feature detection (tcgen05 availability) -------------------
#if defined(__CUDA_ARCH__) && (__CUDA_ARCH__ == 1000 || __CUDA_ARCH__ == 1030) && \
    (defined(__CUDA_ARCH_FEAT_SM100_ALL) || defined(__CUDA_ARCH_FEAT_SM103_ALL) || \
     defined(__CUDA_ARCH_SPECIFIC__) || defined(__CUDA_ARCH_FAMILY_SPECIFIC__))
#define TC_PATH 1
#else
#define TC_PATH 0
#endif

// ---------------- scratch -------------------------------------------------------
__device__ float g_xa[(size_t)N_TOK * DM];               // fallback tf32 A (token order)
__device__ float g_h[(size_t)N_TOK * HM];                // fallback tf32 h
__device__ float g_w1t[(size_t)EM * DM * HM];            // fallback tf32 W1
__device__ float g_w2t[(size_t)EM * HM * DM];            // fallback tf32 W2
__device__ __nv_bfloat16 g_a_hi[(size_t)N_TOK * DM];     // tc: A hi/lo (token order)
__device__ __nv_bfloat16 g_a_lo[(size_t)N_TOK * DM];
// tc: weight blobs = exact swizzled SMEM stage images
__device__ __align__(16) uint4 g_w1b[(size_t)EM * 32 * 2048];  // 8MB
__device__ __align__(16) uint4 g_w2b[(size_t)EM * 64 * 1024];  // 8MB
__device__ int g_top1[N_TOK];
__device__ int g_rank[N_TOK];
__device__ int g_perm[N_TOK];
__device__ int g_counts[EM];

// ---------------- helpers -------------------------------------------------------
__device__ __forceinline__ uint32_t s2u(const void* p) {
    return (uint32_t)__cvta_generic_to_shared(p);
}
__device__ __forceinline__ uint32_t f2tf(float f) {
    uint32_t u;
    asm("cvt.rna.tf32.f32 %0, %1;" : "=r"(u) : "f"(f));
    return u;
}
__device__ __forceinline__ void cpa16(uint32_t dst, const void* src) {
    asm volatile("cp.async.cg.shared.global [%0], [%1], 16;" ::"r"(dst), "l"(src));
}
__device__ __forceinline__ void cpa_commit() { asm volatile("cp.async.commit_group;"); }
__device__ __forceinline__ void cpa_wait4() { asm volatile("cp.async.wait_group 4;"); }
__device__ __forceinline__ void cpa_wait3() { asm volatile("cp.async.wait_group 3;"); }
__device__ __forceinline__ void cpa_wait2() { asm volatile("cp.async.wait_group 2;"); }
__device__ __forceinline__ void cpa_wait1() { asm volatile("cp.async.wait_group 1;"); }
__device__ __forceinline__ void cpa_wait0() { asm volatile("cp.async.wait_group 0;"); }

__device__ __forceinline__ uint32_t bfpack(__nv_bfloat16 a, __nv_bfloat16 b) {
    uint16_t ua = *(uint16_t*)&a, ub = *(uint16_t*)&b;
    return (uint32_t)ua | ((uint32_t)ub << 16);
}
__device__ __forceinline__ void bfsplit(float v, __nv_bfloat16& h, __nv_bfloat16& l) {
    h = __float2bfloat16(v);
    l = __float2bfloat16(v - __bfloat162float(h));
}

// tile -> (expert, row0, rows) from g_counts
__device__ __forceinline__ bool map_tile(int bx, int& e_out, int& row0_out,
                                         int& rows_out) {
    int acc = 0, off = 0, e = -1, row0 = 0, rows = 0;
#pragma unroll
    for (int i = 0; i < EM; i++) {
        int cnt = g_counts[i];
        int te = (cnt + 127) >> 7;
        if (e < 0 && bx < acc + te) {
            int tm = bx - acc;
            e = i;
            row0 = off + tm * 128;
            rows = cnt - tm * 128;
            if (rows > 128) rows = 128;
        }
        acc += te;
        off += cnt;
    }
    e_out = e;
    row0_out = row0;
    rows_out = rows;
    return e >= 0;
}

// ---------------- 1: fused router + LN + split (one warp per token) ---------------
__global__ __launch_bounds__(256) void k_router(const float* __restrict__ x,
                                                const float* __restrict__ Wg,
                                                const float* __restrict__ ls,
                                                const float* __restrict__ lb) {
    const int warp = threadIdx.x >> 5, lane = threadIdx.x & 31;
    const int n = blockIdx.x * 8 + warp;
    const float4* xr = (const float4*)(x + (size_t)n * DM);
    const float4* wg = (const float4*)Wg;

    float s = 0.f, ss = 0.f;
    float lg[EM];
#pragma unroll
    for (int e = 0; e < EM; e++) lg[e] = 0.f;
    float4 xv[8];
#pragma unroll
    for (int j = 0; j < 8; j++) {
        float4 v = xr[lane + 32 * j];
        xv[j] = v;
        s += v.x + v.y + v.z + v.w;
        ss += v.x * v.x + v.y * v.y + v.z * v.z + v.w * v.w;
#pragma unroll
        for (int e = 0; e < EM; e++) {
            float4 w = wg[e * 256 + lane + 32 * j];
            lg[e] += v.x * w.x + v.y * w.y + v.z * w.z + v.w * w.w;
        }
    }
#pragma unroll
    for (int o = 16; o > 0; o >>= 1) {
        s  += __shfl_xor_sync(0xffffffffu, s, o);
        ss += __shfl_xor_sync(0xffffffffu, ss, o);
#pragma unroll
        for (int e = 0; e < EM; e++)
            lg[e] += __shfl_xor_sync(0xffffffffu, lg[e], o);
    }
    float mu = s / (float)DM;
    float var = ss / (float)DM - mu * mu;
    float rs = rsqrtf(var + 1e-5f);
    int best = 0;
    float bv = lg[0];
#pragma unroll
    for (int e = 1; e < EM; e++)
        if (lg[e] > bv) { bv = lg[e]; best = e; }
    if (lane == 0) {
        g_top1[n] = best;
        g_rank[n] = atomicAdd(&g_counts[best], 1);
    }
    const float4* lsr = (const float4*)(ls + (size_t)best * DM);
    const float4* lbr = (const float4*)(lb + (size_t)best * DM);
#pragma unroll
    for (int j = 0; j < 8; j++) {
        float4 sv = lsr[lane + 32 * j];
        float4 bb = lbr[lane + 32 * j];
        float v0 = (xv[j].x - mu) * rs * sv.x + bb.x;
        float v1 = (xv[j].y - mu) * rs * sv.y + bb.y;
        float v2 = (xv[j].z - mu) * rs * sv.z + bb.z;
        float v3 = (xv[j].w - mu) * rs * sv.w + bb.w;
        size_t idx = (size_t)n * DM + 4 * (lane + 32 * j);
#if TC_PATH
        __nv_bfloat16 h0, h1, h2, h3, l0, l1, l2, l3;
        bfsplit(v0, h0, l0);
        bfsplit(v1, h1, l1);
        bfsplit(v2, h2, l2);
        bfsplit(v3, h3, l3);
        *(uint2*)(g_a_hi + idx) = make_uint2(bfpack(h0, h1), bfpack(h2, h3));
        *(uint2*)(g_a_lo + idx) = make_uint2(bfpack(l0, l1), bfpack(l2, l3));
#else
        float4 o;
        o.x = __uint_as_float(f2tf(v0));
        o.y = __uint_as_float(f2tf(v1));
        o.z = __uint_as_float(f2tf(v2));
        o.w = __uint_as_float(f2tf(v3));
        *(float4*)(g_xa + idx) = o;
#endif
    }
}

// ---------------- 2: perm --------------------------------------------------------
__global__ __launch_bounds__(256) void k_perm() {
    int n = blockIdx.x * 256 + threadIdx.x;
    int e = g_top1[n];
    int off = 0;
#pragma unroll
    for (int i = 0; i < EM; i++)
        if (i < e) off += g_counts[i];
    g_perm[off + g_rank[n]] = n;
}

// ---------------- 3: weight prep (-> swizzled stage blobs) -------------------------
#define SWZH(o) ((o) ^ (((o) >> 3) & 0x70u))
__global__ __launch_bounds__(256) void k_wprep(const float* __restrict__ W1,
                                               const float* __restrict__ W2) {
#if TC_PATH
    __shared__ float t[32][33];
    const int e = blockIdx.y;
    const int bx = blockIdx.x;
    const int tid = threadIdx.x;
    const int tx = tid & 31, ty = tid >> 5;

    const float* src;
    uint4* dstBlob;
    int colbase, rowloc_base;
    if (bx < 256) {
        int s = bx >> 3, rblk = bx & 7;
        src = W1 + (size_t)e * DM * HM + (size_t)(s * 32) * HM + rblk * 32;
        dstBlob = g_w1b + (size_t)(e * 32 + s) * 2048;
        colbase = HM;
        rowloc_base = rblk * 32;
    } else {
        int idx = bx - 256;
        int g = idx >> 2, rblk2 = idx & 3;
        int cch = g >> 3, s2 = g & 7;
        src = W2 + (size_t)e * HM * DM + (size_t)(s2 * 32) * DM + cch * 128 + rblk2 * 32;
        dstBlob = g_w2b + (size_t)(e * 64 + g) * 1024;
        colbase = DM;
        rowloc_base = rblk2 * 32;
    }
#pragma unroll
    for (int j = 0; j < 4; j++)
        t[ty + 8 * j][tx] = src[(size_t)(ty + 8 * j) * colbase + tx];
    __syncthreads();
    const int rloc = tid >> 3, c8 = tid & 7;
    const int kc = (c8 & 3) * 8;
    const bool hi = c8 < 4;
    uint32_t w[4];
#pragma unroll
    for (int q = 0; q < 4; q++) {
        __nv_bfloat16 ha, la, hb, lc;
        bfsplit(t[kc + 2 * q][rloc], ha, la);
        bfsplit(t[kc + 2 * q + 1][rloc], hb, lc);
        w[q] = hi ? bfpack(ha, hb) : bfpack(la, lc);
    }
    uint32_t off = SWZH((uint32_t)((rowloc_base + rloc) * 128 + c8 * 16));
    dstBlob[off >> 4] = make_uint4(w[0], w[1], w[2], w[3]);
#else
    const int HALF = EM * DM * HM / 4;
    int id = (blockIdx.y * 512 + blockIdx.x) * 256 + threadIdx.x;
    const float4* src = (id < HALF) ? (const float4*)W1 : (const float4*)W2;
    float4* dst = (id < HALF) ? (float4*)g_w1t : (float4*)g_w2t;
    int i = (id < HALF) ? id : id - HALF;
    float4 v = src[i];
    float4 o;
    o.x = __uint_as_float(f2tf(v.x));
    o.y = __uint_as_float(f2tf(v.y));
    o.z = __uint_as_float(f2tf(v.z));
    o.w = __uint_as_float(f2tf(v.w));
    dst[i] = o;
#endif
}

// =====================================================================================
// tcgen05 machinery
// =====================================================================================
#if TC_PATH
#define SWZ(o) ((o) ^ (((o) >> 3) & 0x70u))
__device__ __forceinline__ bool elect_one() {
    uint32_t pred;
    asm volatile(
        "{\n\t.reg .pred p;\n\telect.sync _|p, 0xFFFFFFFF;\n\tselp.b32 %0, 1, 0, p;\n\t}"
        : "=r"(pred));
    return pred != 0;
}
__device__ __forceinline__ void mbar_wait(uint32_t addr, uint32_t parity) {
    asm volatile(
        "{\n\t"
        ".reg .pred P;\n\t"
        "LAB_%=:\n\t"
        "mbarrier.try_wait.parity.acquire.cta.shared::cta.b64 P, [%0], %1;\n\t"
        "@!P bra LAB_%=;\n\t"
        "}"
        :: "r"(addr), "r"(parity) : "memory");
}
__device__ __forceinline__ void expect_tx(uint32_t mbar, uint32_t bytes) {
    asm volatile("mbarrier.arrive.expect_tx.shared.b64 _, [%0], %1;"
                 :: "r"(mbar), "r"(bytes) : "memory");
}
__device__ __forceinline__ void bulk_g2s(uint32_t dst, const void* src,
                                         uint32_t bytes, uint32_t mbar) {
    asm volatile(
        "cp.async.bulk.shared::cta.global.mbarrier::complete_tx::bytes [%0], [%1], %2, [%3];"
        :: "r"(dst), "l"(src), "r"(bytes), "r"(mbar) : "memory");
}
__device__ __forceinline__ void mma_ss_f16(uint32_t d, uint64_t ad, uint64_t bd,
                                           uint32_t idesc, uint32_t en) {
    asm volatile(
        "{\n\t"
        ".reg .pred p;\n\t"
        "setp.ne.u32 p, %4, 0;\n\t"
        "tcgen05.mma.cta_group::1.kind::f16 [%0], %1, %2, %3, {%5, %5, %5, %5}, p;\n\t"
        "}"
        :: "r"(d), "l"(ad), "l"(bd), "r"(idesc), "r"(en), "r"(0u)
        : "memory");
}
#define LDTM32(r, a)                                                         \
    asm volatile(                                                            \
        "tcgen05.ld.sync.aligned.32x32b.x32.b32 "                            \
        "{%0, %1, %2, %3, %4, %5, %6, %7, "                                  \
        " %8, %9, %10, %11, %12, %13, %14, %15, "                            \
        " %16, %17, %18, %19, %20, %21, %22, %23, "                          \
        " %24, %25, %26, %27, %28, %29, %30, %31}, [%32];"                   \
        : "=r"((r)[0]), "=r"((r)[1]), "=r"((r)[2]), "=r"((r)[3]),            \
          "=r"((r)[4]), "=r"((r)[5]), "=r"((r)[6]), "=r"((r)[7]),            \
          "=r"((r)[8]), "=r"((r)[9]), "=r"((r)[10]), "=r"((r)[11]),          \
          "=r"((r)[12]), "=r"((r)[13]), "=r"((r)[14]), "=r"((r)[15]),        \
          "=r"((r)[16]), "=r"((r)[17]), "=r"((r)[18]), "=r"((r)[19]),        \
          "=r"((r)[20]), "=r"((r)[21]), "=r"((r)[22]), "=r"((r)[23]),        \
          "=r"((r)[24]), "=r"((r)[25]), "=r"((r)[26]), "=r"((r)[27]),        \
          "=r"((r)[28]), "=r"((r)[29]), "=r"((r)[30]), "=r"((r)[31])         \
        : "r"(a))

#define DESCB ((2ULL << 61) | (1ULL << 46) | (64ULL << 32) | (1ULL << 16))
#define IDESC1 0x8400490u   // N=256, M=128
#define IDESC2 0x8200490u   // N=128, M=128
#define A_SLOT 16384        // one A stage (128 rows x 128B), ring of 6: 0..96K
#define B1_BASE 98304       // GEMM1 B ring: 4 x 32KB: 96K..224K
#define STG1B 32768
#define H_BLK 16384         // h blocks: sb+0..128K (after GEMM1 done)
#define B2_BASE 131072      // GEMM2 B ring: 3 x 32KB: 128K..224K
#define STG2B 32768
#endif

#define SMEM_ALLOC (229376 + 1024)   // 224KB rings + align pad

// fallback tiling
#define BK 32
#define AS_STR 36
#define BS_STR 136
#define A_STAGE (128 * AS_STR)
#define B_STAGE (BK * BS_STR)
#define NSTG 3

#if !TC_PATH
__device__ __forceinline__ void mma8(float* c, const uint32_t* a, const uint32_t* b) {
    asm volatile(
        "mma.sync.aligned.m16n8k8.row.col.f32.tf32.tf32.f32 "
        "{%0,%1,%2,%3},{%4,%5,%6,%7},{%8,%9},{%0,%1,%2,%3};"
        : "+f"(c[0]), "+f"(c[1]), "+f"(c[2]), "+f"(c[3])
        : "r"(a[0]), "r"(a[1]), "r"(a[2]), "r"(a[3]), "r"(b[0]), "r"(b[1]));
}
__device__ __forceinline__ void fb_load_stage(uint32_t smem_u32, int stg,
                                              const float* Ag, int ldA, int row0,
                                              int rows, const int* prow,
                                              const float* Bg, int ldB,
                                              int col0, int k0, int tid) {
    uint32_t as_b = smem_u32 + (uint32_t)stg * (A_STAGE * 4);
    uint32_t bs_b = smem_u32 + (uint32_t)(NSTG * A_STAGE + stg * B_STAGE) * 4;
#pragma unroll
    for (int i = 0; i < 4; i++) {
        int id = tid + 256 * i;
        int r = id >> 3, kc = (id & 7) * 4;
        int rr = (r < rows) ? r : rows - 1;
        int grow = prow ? prow[rr] : (row0 + rr);
        cpa16(as_b + (uint32_t)(r * AS_STR + kc) * 4,
              Ag + (size_t)grow * ldA + k0 + kc);
    }
#pragma unroll
    for (int i = 0; i < 4; i++) {
        int id = tid + 256 * i;
        int kr = id >> 5, nc = (id & 31) * 4;
        cpa16(bs_b + (uint32_t)(kr * BS_STR + nc) * 4,
              Bg + (size_t)(k0 + kr) * ldB + col0 + nc);
    }
}
__device__ __forceinline__ void fb_compute_stage(const uint32_t* smem, int stg,
                                                 int wm, int wn, int g, int t,
                                                 float c[2][8][4]) {
    const uint32_t* As = smem + stg * A_STAGE;
    const uint32_t* Bs = smem + NSTG * A_STAGE + stg * B_STAGE;
#pragma unroll
    for (int ks = 0; ks < BK; ks += 8) {
        uint32_t a[2][4], b[8][2];
#pragma unroll
        for (int mt = 0; mt < 2; mt++) {
            int m = wm * 32 + mt * 16 + g;
            a[mt][0] = As[m * AS_STR + ks + t];
            a[mt][1] = As[(m + 8) * AS_STR + ks + t];
            a[mt][2] = As[m * AS_STR + ks + t + 4];
            a[mt][3] = As[(m + 8) * AS_STR + ks + t + 4];
        }
#pragma unroll
        for (int nt = 0; nt < 8; nt++) {
            int n = wn * 64 + nt * 8 + g;
            b[nt][0] = Bs[(ks + t) * BS_STR + n];
            b[nt][1] = Bs[(ks + t + 4) * BS_STR + n];
        }
#pragma unroll
        for (int mt = 0; mt < 2; mt++)
#pragma unroll
            for (int nt = 0; nt < 8; nt++)
                mma8(c[mt][nt], a[mt], b[nt]);
    }
}
#endif

// ---------------- 4: fused FFN (GEMM1 -> GELU -> SMEM h -> GEMM2) ------------------
// grid 136, 256 threads
__global__ __launch_bounds__(256) void k_ffn(const float* __restrict__ b1,
                                             const float* __restrict__ b2,
                                             float* __restrict__ out) {
    extern __shared__ __align__(16) char dsm[];

    int e, row0, rows;
    bool valid = map_tile(blockIdx.x, e, row0, rows);
    const int tid = threadIdx.x, wid = tid >> 5, lane = tid & 31;

#if TC_PATH
    if (valid) {
    __shared__ uint32_t s_tslot;
    // [0,1]=commit gating, [2..5]=tx (B bulk), [6]=chunk
    __shared__ __align__(8) uint64_t s_mbar[7];
    uint32_t sb = s2u(dsm);
    sb = (sb + 1023u) & ~1023u;
    const uint32_t mb0 = s2u(&s_mbar[0]);
    const uint32_t mb1 = s2u(&s_mbar[1]);
    const uint32_t mbT = s2u(&s_mbar[2]);
    const uint32_t mbC = s2u(&s_mbar[6]);
    const uint32_t tslot = s2u(&s_tslot);

    if (wid == 0) {
        asm volatile("tcgen05.alloc.cta_group::1.sync.aligned.shared::cta.b32 [%0], %1;"
                     :: "r"(tslot), "r"(256) : "memory");
        asm volatile("tcgen05.relinquish_alloc_permit.cta_group::1.sync.aligned;");
    }
    if (tid == 0) {
        asm volatile("mbarrier.init.shared.b64 [%0], 1;" :: "r"(mb0) : "memory");
        asm volatile("mbarrier.init.shared.b64 [%0], 1;" :: "r"(mb1) : "memory");
#pragma unroll
        for (int i = 0; i < 4; i++)
            asm volatile("mbarrier.init.shared.b64 [%0], 1;" :: "r"(mbT + 8 * i) : "memory");
        asm volatile("mbarrier.init.shared.b64 [%0], 1;" :: "r"(mbC) : "memory");
    }
    __syncthreads();
    uint32_t tb;
    asm volatile("ld.shared.b32 %0, [%1];" : "=r"(tb) : "r"(tslot));
    uint32_t ph[2] = {0u, 0u};
    uint32_t fph = 0u;   // tx barrier parity bits (elect only)
    uint32_t cph = 0u;

    const uint4* w1blob = g_w1b + (size_t)e * 32 * 2048;
    const uint4* w2blob = g_w2b + (size_t)e * 64 * 1024;

    // ---------------- GEMM1: A (cp.async ring-6) x W1 blob (bulk) -------------------
    const int c8 = tid & 7;
    const bool chi = (c8 < 4);
    {
        const __nv_bfloat16* Asrc[4];
        uint32_t Adst[4];
        const int cq = (c8 & 3) * 8;
#pragma unroll
        for (int i = 0; i < 4; i++) {
            int r = (tid >> 3) + 32 * i;
            int rr = (r < rows) ? r : rows - 1;
            int tok = g_perm[row0 + rr];
            Asrc[i] = (chi ? g_a_hi : g_a_lo) + (size_t)tok * DM + cq;
            Adst[i] = SWZ((uint32_t)(r * 128 + c8 * 16));
        }
        auto loadA = [&](int s) {
            uint32_t base = sb + (uint32_t)(s % 6) * A_SLOT;
            int k0 = s * 32;
#pragma unroll
            for (int i = 0; i < 4; i++)
                cpa16(base + Adst[i], Asrc[i] + k0);
            cpa_commit();
        };

        const int S = DM / 32;  // 32
        int ni1 = 0;
        loadA(0);
        loadA(1);
        loadA(2);
        loadA(3);
        for (int s = 0; s < S; s++) {
            if (s >= 2) {
                uint32_t m = (s & 1) ? mb1 : mb0;
                mbar_wait(m, ph[s & 1]);
                ph[s & 1] ^= 1;
            }
            if (s + 4 < S) loadA(s + 4);
            if (s + 4 < S) cpa_wait4();
            else if (s + 3 < S) cpa_wait3();
            else if (s + 2 < S) cpa_wait2();
            else if (s + 1 < S) cpa_wait1();
            else cpa_wait0();
            __syncthreads();
            if (wid == 0) {
                asm volatile("fence.proxy.async.shared::cta;" ::: "memory");
                if (elect_one()) {
                    while (ni1 < S && ni1 <= s + 2) {
                        uint32_t mt = mbT + 8 * (ni1 & 3);
                        expect_tx(mt, 32768u);
                        bulk_g2s(sb + B1_BASE + (uint32_t)(ni1 & 3) * STG1B,
                                 w1blob + (size_t)ni1 * 2048, 32768u, mt);
                        ni1++;
                    }
                    mbar_wait(mbT + 8 * (s & 3), (fph >> (s & 3)) & 1u);
                    fph ^= 1u << (s & 3);
                    uint64_t ab = DESCB |
                        ((uint64_t)((sb + (uint32_t)(s % 6) * A_SLOT) >> 4) & 0x3FFF);
                    uint64_t bb = DESCB |
                        ((uint64_t)((sb + B1_BASE + (uint32_t)(s & 3) * STG1B) >> 4) & 0x3FFF);
#pragma unroll
                    for (int ks = 0; ks < 2; ks++) {
                        uint64_t ah = ab + 2 * ks, al = ab + 4 + 2 * ks;
                        uint64_t bh = bb + 2 * ks, bl = bb + 4 + 2 * ks;
                        mma_ss_f16(tb, ah, bh, IDESC1, (s == 0 && ks == 0) ? 0u : 1u);
                        mma_ss_f16(tb, ah, bl, IDESC1, 1u);
                        mma_ss_f16(tb, al, bh, IDESC1, 1u);
                    }
                    uint32_t m = (s & 1) ? mb1 : mb0;
                    asm volatile(
                        "tcgen05.commit.cta_group::1.mbarrier::arrive::one.shared::cluster.b64 [%0];"
                        :: "r"(m) : "memory");
                }
            }
        }
        {
            mbar_wait(mb0, ph[0]);
            ph[0] ^= 1;
            mbar_wait(mb1, ph[1]);
            ph[1] ^= 1;
        }
        asm volatile("tcgen05.fence::after_thread_sync;" ::: "memory");
    }

    // ---------------- GEMM1 epilogue: bias + GELU -> SMEM h -------------------------
    {
        int rl = (wid & 3) * 32 + lane;
        int ccb = (wid >> 2) * 4;
        const float* bbp = b1 + e * HM;
#pragma unroll 1
        for (int ci = 0; ci < 4; ci++) {
            int cc = ccb + ci;
            uint32_t r[32];
            LDTM32(r, tb + cc * 32);
            asm volatile("tcgen05.wait::ld.sync.aligned;" ::: "memory");
            uint32_t whi[16], wlo[16];
#pragma unroll
            for (int p = 0; p < 16; p++) {
                float v0 = __uint_as_float(r[2 * p]) + __ldg(&bbp[cc * 32 + 2 * p]);
                float v1 = __uint_as_float(r[2 * p + 1]) + __ldg(&bbp[cc * 32 + 2 * p + 1]);
                v0 = 0.5f * v0 * (1.f + erff(v0 * 0.70710678118654752f));
                v1 = 0.5f * v1 * (1.f + erff(v1 * 0.70710678118654752f));
                __nv_bfloat16 h0, h1, l0, l1;
                bfsplit(v0, h0, l0);
                bfsplit(v1, h1, l1);
                whi[p] = bfpack(h0, h1);
                wlo[p] = bfpack(l0, l1);
            }
            uint32_t blk = sb + (uint32_t)cc * H_BLK;
#pragma unroll
            for (int q = 0; q < 4; q++) {
                uint32_t ohi = blk + SWZ((uint32_t)(rl * 128 + 16 * q));
                uint32_t olo = blk + SWZ((uint32_t)(rl * 128 + 64 + 16 * q));
                asm volatile("st.shared.v4.b32 [%0], {%1,%2,%3,%4};"
                             :: "r"(ohi), "r"(whi[4 * q]), "r"(whi[4 * q + 1]),
                                "r"(whi[4 * q + 2]), "r"(whi[4 * q + 3]) : "memory");
                asm volatile("st.shared.v4.b32 [%0], {%1,%2,%3,%4};"
                             :: "r"(olo), "r"(wlo[4 * q]), "r"(wlo[4 * q + 1]),
                                "r"(wlo[4 * q + 2]), "r"(wlo[4 * q + 3]) : "memory");
            }
        }
    }
    asm volatile("fence.proxy.async.shared::cta;" ::: "memory");
    __syncthreads();

    // ---------------- GEMM2: h(SMEM) x W2 blobs (KC=64, 32 stages) -> out ------------
    {
        int rl = (wid & 3) * 32 + lane;
        bool ok = rl < rows;
        int tok = ok ? g_perm[row0 + rl] : 0;
        float* orow = out + (size_t)tok * DM;
        int ni2 = 0;

        for (int cch = 0; cch < 8; cch++) {
            if (wid == 0 && elect_one()) {
#pragma unroll 1
                for (int p = 0; p < 4; p++) {
                    int t = cch * 4 + p;
                    if (t >= 2) {
                        uint32_t m = (t & 1) ? mb1 : mb0;
                        mbar_wait(m, ph[t & 1]);
                        ph[t & 1] ^= 1;
                    }
                    // issue B bulks up to t+1 (slot ni2%3 freed by commit(ni2-3) <= t-2)
                    while (ni2 < 32 && ni2 <= t + 1) {
                        int sl = ni2 % 3;
                        uint32_t mt = mbT + 8 * sl;
                        expect_tx(mt, 32768u);
                        bulk_g2s(sb + B2_BASE + (uint32_t)sl * STG2B,
                                 w2blob + (size_t)ni2 * 2048, 32768u, mt);
                        ni2++;
                    }
                    int tsl = t % 3;
                    mbar_wait(mbT + 8 * tsl, (fph >> tsl) & 1u);
                    fph ^= 1u << tsl;
#pragma unroll
                    for (int kk = 0; kk < 2; kk++) {
                        uint64_t ab = DESCB |
                            ((uint64_t)((sb + (uint32_t)(p * 2 + kk) * H_BLK) >> 4) & 0x3FFF);
                        uint64_t bbd = DESCB |
                            ((uint64_t)((sb + B2_BASE + (uint32_t)tsl * STG2B +
                                         (uint32_t)kk * 16384u) >> 4) & 0x3FFF);
#pragma unroll
                        for (int ks = 0; ks < 2; ks++) {
                            uint64_t ah = ab + 2 * ks, al = ab + 4 + 2 * ks;
                            uint64_t bh = bbd + 2 * ks, bl = bbd + 4 + 2 * ks;
                            uint32_t en = (p == 0 && kk == 0 && ks == 0) ? 0u : 1u;
                            mma_ss_f16(tb, ah, bh, IDESC2, en);
                            mma_ss_f16(tb, ah, bl, IDESC2, 1u);
                            mma_ss_f16(tb, al, bh, IDESC2, 1u);
                        }
                    }
                    uint32_t m = (t & 1) ? mb1 : mb0;
                    asm volatile(
                        "tcgen05.commit.cta_group::1.mbarrier::arrive::one.shared::cluster.b64 [%0];"
                        :: "r"(m) : "memory");
                    if (p == 3)
                        asm volatile(
                            "tcgen05.commit.cta_group::1.mbarrier::arrive::one.shared::cluster.b64 [%0];"
                            :: "r"(mbC) : "memory");
                }
            }
            // chunk complete: all threads
            mbar_wait(mbC, cph);
            cph ^= 1u;
            asm volatile("tcgen05.fence::after_thread_sync;" ::: "memory");
            {
                int colh = (wid >> 2) * 64;
                const float* bbp = b2 + e * DM + cch * 128 + colh;
#pragma unroll 1
                for (int half = 0; half < 2; half++) {
                    uint32_t r[32];
                    LDTM32(r, tb + colh + half * 32);
                    asm volatile("tcgen05.wait::ld.sync.aligned;" ::: "memory");
                    if (ok) {
#pragma unroll
                        for (int q = 0; q < 8; q++) {
                            float4 v;
                            v.x = __uint_as_float(r[4 * q + 0]) + __ldg(&bbp[half * 32 + 4 * q + 0]);
                            v.y = __uint_as_float(r[4 * q + 1]) + __ldg(&bbp[half * 32 + 4 * q + 1]);
                            v.z = __uint_as_float(r[4 * q + 2]) + __ldg(&bbp[half * 32 + 4 * q + 2]);
                            v.w = __uint_as_float(r[4 * q + 3]) + __ldg(&bbp[half * 32 + 4 * q + 3]);
                            *(float4*)(orow + cch * 128 + colh + half * 32 + 4 * q) = v;
                        }
                    }
                }
            }
            __syncthreads();  // LDTM done in all warps before next chunk's MMAs
        }
    }
    if (wid == 0)
        asm volatile("tcgen05.dealloc.cta_group::1.sync.aligned.b32 %0, %1;"
                     :: "r"(tb), "r"(256));
    }  // valid
#else
    if (valid) {
    uint32_t* smem = (uint32_t*)dsm;
    const uint32_t smem_u32 = s2u(dsm);
    const int* prow = g_perm + row0;
    const int w = wid, wm = w >> 1, wn = w & 1;
    const int g = lane >> 2, tt = lane & 3;

    for (int hseg = 0; hseg < 2; hseg++) {
        int col0 = hseg * 128;
        const float* Ag = g_xa;
        const float* Bg = g_w1t + (size_t)e * DM * HM;
        float cacc[2][8][4];
#pragma unroll
        for (int i = 0; i < 2; i++)
#pragma unroll
            for (int j = 0; j < 8; j++)
#pragma unroll
                for (int q = 0; q < 4; q++) cacc[i][j][q] = 0.f;
        const int S = DM / BK;
        __syncthreads();
        fb_load_stage(smem_u32, 0, Ag, DM, row0, rows, prow, Bg, HM, col0, 0, tid);
        cpa_commit();
        fb_load_stage(smem_u32, 1, Ag, DM, row0, rows, prow, Bg, HM, col0, BK, tid);
        cpa_commit();
        for (int s = 0; s < S; s++) {
            if (s + 1 < S) cpa_wait1(); else cpa_wait0();
            __syncthreads();
            if (s + 2 < S) {
                fb_load_stage(smem_u32, (s + 2) % NSTG, Ag, DM, row0, rows, prow,
                              Bg, HM, col0, (s + 2) * BK, tid);
                cpa_commit();
            }
            fb_compute_stage(smem, s % NSTG, wm, wn, g, tt, cacc);
        }
#pragma unroll
        for (int mt = 0; mt < 2; mt++) {
            int rl0 = wm * 32 + mt * 16 + g;
#pragma unroll
            for (int half = 0; half < 2; half++) {
                int rl = rl0 + 8 * half;
                if (rl < rows) {
                    size_t orw = (size_t)(row0 + rl) * HM;
#pragma unroll
                    for (int nt = 0; nt < 8; nt++) {
                        int col = col0 + wn * 64 + nt * 8 + 2 * tt;
                        float v0 = cacc[mt][nt][2 * half + 0] + __ldg(&b1[e * HM + col]);
                        float v1 = cacc[mt][nt][2 * half + 1] + __ldg(&b1[e * HM + col + 1]);
                        v0 = 0.5f * v0 * (1.f + erff(v0 * 0.70710678118654752f));
                        v1 = 0.5f * v1 * (1.f + erff(v1 * 0.70710678118654752f));
                        float2 o = make_float2(__uint_as_float(f2tf(v0)),
                                               __uint_as_float(f2tf(v1)));
                        *(float2*)&g_h[orw + col] = o;
                    }
                }
            }
        }
        __syncthreads();
    }

    for (int ct = 0; ct < 8; ct++) {
        int col0 = ct * 128;
        const float* Ag = g_h;
        const float* Bg = g_w2t + (size_t)e * HM * DM;
        float cacc[2][8][4];
#pragma unroll
        for (int i = 0; i < 2; i++)
#pragma unroll
            for (int j = 0; j < 8; j++)
#pragma unroll
                for (int q = 0; q < 4; q++) cacc[i][j][q] = 0.f;
        const int S = HM / BK;
        __syncthreads();
        fb_load_stage(smem_u32, 0, Ag, HM, row0, rows, nullptr, Bg, DM, col0, 0, tid);
        cpa_commit();
        fb_load_stage(smem_u32, 1, Ag, HM, row0, rows, nullptr, Bg, DM, col0, BK, tid);
        cpa_commit();
        for (int s = 0; s < S; s++) {
            if (s + 1 < S) cpa_wait1(); else cpa_wait0();
            __syncthreads();
            if (s + 2 < S) {
                fb_load_stage(smem_u32, (s + 2) % NSTG, Ag, HM, row0, rows, nullptr,
                              Bg, DM, col0, (s + 2) * BK, tid);
                cpa_commit();
            }
            fb_compute_stage(smem, s % NSTG, wm, wn, g, tt, cacc);
        }
#pragma unroll
        for (int mt = 0; mt < 2; mt++) {
            int rl0 = wm * 32 + mt * 16 + g;
#pragma unroll
            for (int half = 0; half < 2; half++) {
                int rl = rl0 + 8 * half;
                if (rl < rows) {
                    int tok = g_perm[row0 + rl];
                    float* orw = out + (size_t)tok * DM;
#pragma unroll
                    for (int nt = 0; nt < 8; nt++) {
                        int col = col0 + wn * 64 + nt * 8 + 2 * tt;
                        float v0 = cacc[mt][nt][2 * half + 0] + __ldg(&b2[e * DM + col]);
                        float v1 = cacc[mt][nt][2 * half + 1] + __ldg(&b2[e * DM + col + 1]);
                        *(float2*)&orw[col] = make_float2(v0, v1);
                    }
                }
            }
        }
        __syncthreads();
    }
    }  // valid
#endif
    // reset counters for next graph replay
    __syncthreads();
    if (blockIdx.x == 0 && tid < EM) g_counts[tid] = 0;
}

// ---------------- launch -----------------------------------------------------------------
extern "C" void kernel_launch(void* const* d_in, const int* in_sizes, int n_in,
                              void* d_out, int out_size) {
    (void)in_sizes; (void)n_in; (void)out_size;
    const float* x  = (const float*)d_in[0];
    const float* Wg = (const float*)d_in[1];
    const float* ls = (const float*)d_in[2];
    const float* lb = (const float*)d_in[3];
    const float* W1 = (const float*)d_in[4];
    const float* b1 = (const float*)d_in[5];
    const float* W2 = (const float*)d_in[6];
    const float* b2 = (const float*)d_in[7];
    float* out = (float*)d_out;

    cudaFuncSetAttribute(k_ffn, cudaFuncAttributeMaxDynamicSharedMemorySize, SMEM_ALLOC);

    static cudaStream_t s1 = nullptr;
    static cudaEvent_t ev_fork = nullptr, ev_join = nullptr;
    static bool stream_ok = false;
    static bool tried = false;
    if (!tried) {
        tried = true;
        if (cudaStreamCreateWithFlags(&s1, cudaStreamNonBlocking) == cudaSuccess &&
            cudaEventCreateWithFlags(&ev_fork, cudaEventDisableTiming) == cudaSuccess &&
            cudaEventCreateWithFlags(&ev_join, cudaEventDisableTiming) == cudaSuccess)
            stream_ok = true;
    }

    const int MAX_TILES = (N_TOK / 128) + EM;  // 136

    if (stream_ok) {
        cudaEventRecord(ev_fork, 0);
        cudaStreamWaitEvent(s1, ev_fork, 0);
        k_wprep<<<dim3(512, EM), 256, 0, s1>>>(W1, W2);
        cudaEventRecord(ev_join, s1);
    }
    k_router<<<N_TOK / 8, 256>>>(x, Wg, ls, lb);
    k_perm<<<N_TOK / 256, 256>>>();
    if (stream_ok) {
        cudaStreamWaitEvent(0, ev_join, 0);
    } else {
        k_wprep<<<dim3(512, EM), 256>>>(W1, W2);
    }
    k_ffn<<<MAX_TILES, 256, SMEM_ALLOC>>>(b1, b2, out);
}